// round 2
// baseline (speedup 1.0000x reference)
#include <cuda_runtime.h>
#include <math.h>

#define B  8
#define C  48
#define HH 192
#define WW 192
#define NN (HH*WW)   // 36864

// ---------------- scratch (no allocations allowed) ----------------
__device__ float  g_G[4*B*C*C];        // Gram matrices  [s][b][c][d]
__device__ float  g_P[B*C*4*C];        // P              [b][co][s][e]  (row of 192 per (b,co))
__device__ float  g_y1[B*C*NN];        // fuse conv output (pre-BN)
__device__ double g_stats[4*C];        // sum1, sq1, sum2, sq2
__device__ float  g_bn[4*C];           // scale1, shift1, scale2, shift2

// ---------------- zero scratch ----------------
__global__ void k_zero() {
    int i = blockIdx.x * 256 + threadIdx.x;
    if (i < 4*B*C*C) g_G[i] = 0.f;
    if (i < 4*C)     g_stats[i] = 0.0;
}

// ---------------- pass A: Gram matrices ----------------
// G[s][b][c][d] = sum_n xa[b,c,n] * fs[b,d,n]   (s=0 uses fs=xa)
__global__ __launch_bounds__(256) void k_gram(const float* __restrict__ xa,
                                              const float* __restrict__ xb,
                                              const float* __restrict__ xc,
                                              const float* __restrict__ xd) {
    __shared__ float sX[4][64][48];   // [tensor][n][c]  = 48KB exactly
    const int b     = blockIdx.y;
    const int chunk = blockIdx.x;          // 72 chunks of 512 n
    const int tid = threadIdx.x;
    const int tx = tid & 15, ty = tid >> 4;

    float acc[4][3][3];
    #pragma unroll
    for (int s = 0; s < 4; s++)
        #pragma unroll
        for (int i = 0; i < 3; i++)
            #pragma unroll
            for (int j = 0; j < 3; j++) acc[s][i][j] = 0.f;

    const size_t base = (size_t)b * C * NN + (size_t)chunk * 512;

    for (int tile = 0; tile < 8; tile++) {
        const int n0 = tile * 64;
        for (int idx = tid; idx < 48*64; idx += 256) {
            const int c = idx >> 6, nl = idx & 63;
            const size_t g = base + (size_t)c * NN + n0 + nl;
            sX[0][nl][c] = xa[g];
            sX[1][nl][c] = xb[g];
            sX[2][nl][c] = xc[g];
            sX[3][nl][c] = xd[g];
        }
        __syncthreads();
        for (int n = 0; n < 64; n++) {
            const float a0 = sX[0][n][ty], a1 = sX[0][n][ty+16], a2 = sX[0][n][ty+32];
            #pragma unroll
            for (int s = 0; s < 4; s++) {
                const float b0 = sX[s][n][tx], b1 = sX[s][n][tx+16], b2 = sX[s][n][tx+32];
                acc[s][0][0] += a0*b0; acc[s][0][1] += a0*b1; acc[s][0][2] += a0*b2;
                acc[s][1][0] += a1*b0; acc[s][1][1] += a1*b1; acc[s][1][2] += a1*b2;
                acc[s][2][0] += a2*b0; acc[s][2][1] += a2*b1; acc[s][2][2] += a2*b2;
            }
        }
        __syncthreads();
    }
    #pragma unroll
    for (int s = 0; s < 4; s++)
        #pragma unroll
        for (int i = 0; i < 3; i++)
            #pragma unroll
            for (int j = 0; j < 3; j++) {
                const int c = ty + 16*i, d = tx + 16*j;
                atomicAdd(&g_G[((s*B + b)*C + c)*C + d], acc[s][i][j]);
            }
}

// ---------------- pass B: energy -> attention -> M -> P (tiny) ----------------
__global__ __launch_bounds__(256) void k_attn(const float* __restrict__ Wa,
                                              const float* __restrict__ Wb,
                                              const float* __restrict__ Wc,
                                              const float* __restrict__ Wd,
                                              const float* __restrict__ fuse_w) {
    __shared__ float sA[2304];  // G -> E -> M
    __shared__ float sB[2304];  // Wa -> FW
    __shared__ float sC[2304];  // Ws
    __shared__ float sD[2304];  // T -> attn
    const int s = blockIdx.x, b = blockIdx.y, tid = threadIdx.x;
    const float* Wsp = (s == 0) ? Wa : (s == 1) ? Wb : (s == 2) ? Wc : Wd;

    for (int i = tid; i < 2304; i += 256) {
        sA[i] = g_G[(s*B + b)*2304 + i];
        sB[i] = Wa[i];
        sC[i] = Wsp[i];
    }
    __syncthreads();
    // T[e][d] = sum_f G[e][f] * Ws[d][f]
    for (int i = tid; i < 2304; i += 256) {
        const int e = i / 48, d = i % 48;
        float a = 0.f;
        for (int f = 0; f < 48; f++) a += sA[e*48+f] * sC[d*48+f];
        sD[i] = a;
    }
    __syncthreads();
    // E[c][d] = sum_e Wa[c][e] * T[e][d]   (into sA)
    for (int i = tid; i < 2304; i += 256) {
        const int c = i / 48, d = i % 48;
        float a = 0.f;
        for (int e = 0; e < 48; e++) a += sB[c*48+e] * sD[e*48+d];
        sA[i] = a;
    }
    __syncthreads();
    // attention = softmax(max-E) == softmax(-E): stable via min subtraction (into sD)
    if (tid < 48) {
        const int c = tid;
        float mn = sA[c*48];
        for (int d = 1; d < 48; d++) mn = fminf(mn, sA[c*48+d]);
        float sum = 0.f;
        for (int d = 0; d < 48; d++) { const float v = expf(mn - sA[c*48+d]); sD[c*48+d] = v; sum += v; }
        const float inv = 1.f / sum;
        for (int d = 0; d < 48; d++) sD[c*48+d] *= inv;
    }
    // stage FW (fuse_w slice for branch s) into sB
    for (int i = tid; i < 2304; i += 256) {
        const int co = i / 48, c = i % 48;
        sB[i] = fuse_w[co*192 + s*48 + c];
    }
    __syncthreads();
    // M[co][d] = sum_c FW[co][c] * attn[c][d]   (into sA)
    for (int i = tid; i < 2304; i += 256) {
        const int co = i / 48, d = i % 48;
        float a = 0.f;
        for (int c = 0; c < 48; c++) a += sB[co*48+c] * sD[c*48+d];
        sA[i] = a;
    }
    __syncthreads();
    // P[co][e] = sum_d M[co][d] * Ws[d][e]  -> g_P[b][co][s][e]
    for (int i = tid; i < 2304; i += 256) {
        const int co = i / 48, e = i % 48;
        float a = 0.f;
        for (int d = 0; d < 48; d++) a += sA[co*48+d] * sC[d*48+e];
        g_P[((size_t)b*48 + co)*192 + s*48 + e] = a;
    }
}

// ---------------- pass C: fused 1x1 conv  y1 = P @ [fa;fb;fc;fd] + fuse_b, + BN1 stats ----------------
__global__ __launch_bounds__(256) void k_fuse(const float* __restrict__ xa,
                                              const float* __restrict__ xb,
                                              const float* __restrict__ xc,
                                              const float* __restrict__ xd,
                                              const float* __restrict__ fuse_b) {
    __shared__ float sP[48*192];   // 36864 B
    __shared__ float sF[48*64];    // 12288 B (reused as stats buffer at the end)
    const int b  = blockIdx.y;
    const int n0 = blockIdx.x * 64;
    const int tid = threadIdx.x, tx = tid & 15, ty = tid >> 4;

    for (int i = tid; i < 9216; i += 256) sP[i] = g_P[(size_t)b*9216 + i];

    float acc[3][4];
    #pragma unroll
    for (int i = 0; i < 3; i++)
        #pragma unroll
        for (int j = 0; j < 4; j++) acc[i][j] = 0.f;

    for (int s = 0; s < 4; s++) {
        const float* f = (s == 0) ? xa : (s == 1) ? xb : (s == 2) ? xc : xd;
        __syncthreads();
        for (int idx = tid; idx < 48*64; idx += 256) {
            const int e = idx >> 6, nl = idx & 63;
            sF[idx] = f[((size_t)b*48 + e)*NN + n0 + nl];
        }
        __syncthreads();
        for (int e = 0; e < 48; e++) {
            const float w0 = sP[(ty   )*192 + s*48 + e];
            const float w1 = sP[(ty+16)*192 + s*48 + e];
            const float w2 = sP[(ty+32)*192 + s*48 + e];
            const float x0 = sF[e*64 + tx     ];
            const float x1 = sF[e*64 + tx + 16];
            const float x2 = sF[e*64 + tx + 32];
            const float x3 = sF[e*64 + tx + 48];
            acc[0][0] += w0*x0; acc[0][1] += w0*x1; acc[0][2] += w0*x2; acc[0][3] += w0*x3;
            acc[1][0] += w1*x0; acc[1][1] += w1*x1; acc[1][2] += w1*x2; acc[1][3] += w1*x3;
            acc[2][0] += w2*x0; acc[2][1] += w2*x1; acc[2][2] += w2*x2; acc[2][3] += w2*x3;
        }
    }
    __syncthreads();
    float* ssum = sF;          // reuse
    float* ssq  = sF + 48;
    if (tid < 96) sF[tid] = 0.f;
    __syncthreads();

    #pragma unroll
    for (int i = 0; i < 3; i++) {
        const int co = ty + 16*i;
        const float fb_ = fuse_b[co];
        float lsum = 0.f, lsq = 0.f;
        #pragma unroll
        for (int j = 0; j < 4; j++) {
            const float v = acc[i][j] + fb_;
            g_y1[((size_t)b*48 + co)*NN + n0 + tx + 16*j] = v;
            lsum += v; lsq += v*v;
        }
        for (int o = 8; o > 0; o >>= 1) {
            lsum += __shfl_down_sync(0xffffffffu, lsum, o, 16);
            lsq  += __shfl_down_sync(0xffffffffu, lsq,  o, 16);
        }
        if (tx == 0) { atomicAdd(&ssum[co], lsum); atomicAdd(&ssq[co], lsq); }
    }
    __syncthreads();
    if (tid < 48) {
        atomicAdd(&g_stats[tid],      (double)ssum[tid]);
        atomicAdd(&g_stats[48 + tid], (double)ssq[tid]);
    }
}

// ---------------- BN finalize (tiny) ----------------
__global__ void k_bnfin(const float* __restrict__ gamma, const float* __restrict__ beta, int which) {
    const int c = threadIdx.x;
    if (c >= 48) return;
    const double cnt  = (double)B * NN;
    const double mean = g_stats[which*96 + c] / cnt;
    const double var  = g_stats[which*96 + 48 + c] / cnt - mean*mean;
    const float  sc   = (float)((double)gamma[c] / sqrt(var + 1e-5));
    const float  sh   = beta[c] - (float)mean * sc;
    g_bn[which*96 + c]      = sc;
    g_bn[which*96 + 48 + c] = sh;
}

// ---------------- pass E: 3x3 conv on t = gamma_cam*relu(bn1(y1)) + input ----------------
// writes pre-BN y2 into d_out, accumulates BN2 stats
__global__ __launch_bounds__(256) void k_conv(const float* __restrict__ inp,
                                              const float* __restrict__ out_w,
                                              const float* __restrict__ out_b,
                                              const float* __restrict__ gamma_cam,
                                              float* __restrict__ out) {
    __shared__ float sW[48*9];        // weights for current ci, all co
    __shared__ float sT[10*34];       // padded input tile for current ci
    __shared__ float ssum[48], ssq[48];
    const int b   = blockIdx.z;
    const int hy0 = blockIdx.y * 8;
    const int wx0 = blockIdx.x * 32;
    const int tid = threadIdx.x;
    const int cg  = tid >> 6;         // 4 co-groups of 12
    const int p   = tid & 63;
    const int px  = p & 31;
    const int py2 = p >> 5;           // 0..1, each handles 4 rows
    const float gcam = gamma_cam[0];

    if (tid < 48) { ssum[tid] = 0.f; ssq[tid] = 0.f; }

    float acc[48];
    #pragma unroll
    for (int i = 0; i < 48; i++) acc[i] = 0.f;

    for (int ci = 0; ci < 48; ci++) {
        __syncthreads();
        for (int idx = tid; idx < 432; idx += 256)
            sW[idx] = out_w[((idx/9)*48 + ci)*9 + (idx%9)];
        const float sc = g_bn[ci], sh = g_bn[48 + ci];
        const float* y1p  = g_y1 + ((size_t)b*48 + ci)*NN;
        const float* inpp = inp  + ((size_t)b*48 + ci)*NN;
        for (int idx = tid; idx < 340; idx += 256) {
            const int r = idx / 34, c = idx % 34;
            const int gh = hy0 + r - 1, gw = wx0 + c - 1;
            float v = 0.f;
            if (gh >= 0 && gh < HH && gw >= 0 && gw < WW) {
                const int o = gh*WW + gw;
                float t = y1p[o]*sc + sh;
                t = t > 0.f ? t : 0.f;
                v = gcam*t + inpp[o];
            }
            sT[idx] = v;
        }
        __syncthreads();

        float v[6][3];
        const int baseRow = py2 * 4;
        #pragma unroll
        for (int rr = 0; rr < 6; rr++)
            #pragma unroll
            for (int cc = 0; cc < 3; cc++)
                v[rr][cc] = sT[(baseRow + rr)*34 + px + cc];

        #pragma unroll
        for (int j = 0; j < 12; j++) {
            const float* wp = &sW[(cg*12 + j)*9];
            const float w0=wp[0],w1=wp[1],w2=wp[2],w3=wp[3],w4=wp[4],w5=wp[5],w6=wp[6],w7=wp[7],w8=wp[8];
            #pragma unroll
            for (int r = 0; r < 4; r++) {
                acc[j*4 + r] += w0*v[r  ][0] + w1*v[r  ][1] + w2*v[r  ][2]
                              + w3*v[r+1][0] + w4*v[r+1][1] + w5*v[r+1][2]
                              + w6*v[r+2][0] + w7*v[r+2][1] + w8*v[r+2][2];
            }
        }
    }

    #pragma unroll
    for (int j = 0; j < 12; j++) {
        const int co = cg*12 + j;
        const float bo = out_b[co];
        float lsum = 0.f, lsq = 0.f;
        #pragma unroll
        for (int r = 0; r < 4; r++) {
            const float val = acc[j*4 + r] + bo;
            const int gh = hy0 + py2*4 + r, gw = wx0 + px;
            out[((size_t)b*48 + co)*NN + gh*WW + gw] = val;
            lsum += val; lsq += val*val;
        }
        for (int o = 16; o > 0; o >>= 1) {
            lsum += __shfl_down_sync(0xffffffffu, lsum, o);
            lsq  += __shfl_down_sync(0xffffffffu, lsq,  o);
        }
        if ((tid & 31) == 0) { atomicAdd(&ssum[co], lsum); atomicAdd(&ssq[co], lsq); }
    }
    __syncthreads();
    if (tid < 48) {
        atomicAdd(&g_stats[96 + tid],  (double)ssum[tid]);
        atomicAdd(&g_stats[144 + tid], (double)ssq[tid]);
    }
}

// ---------------- pass G: in-place relu(bn2(y2)) ----------------
__global__ void k_final(float* __restrict__ out) {
    const size_t i = ((size_t)blockIdx.x * 256 + threadIdx.x) * 4;
    const int co = (int)((i / NN) % 48);
    const float sc = g_bn[96 + co], sh = g_bn[144 + co];
    float4 v = *(float4*)(out + i);
    v.x = fmaxf(v.x*sc + sh, 0.f);
    v.y = fmaxf(v.y*sc + sh, 0.f);
    v.z = fmaxf(v.z*sc + sh, 0.f);
    v.w = fmaxf(v.w*sc + sh, 0.f);
    *(float4*)(out + i) = v;
}

// ---------------- launch ----------------
extern "C" void kernel_launch(void* const* d_in, const int* in_sizes, int n_in,
                              void* d_out, int out_size) {
    const float* xa         = (const float*)d_in[0];
    const float* fb         = (const float*)d_in[1];
    const float* fc         = (const float*)d_in[2];
    const float* fd         = (const float*)d_in[3];
    const float* Wa         = (const float*)d_in[4];
    const float* Wb         = (const float*)d_in[5];
    const float* Wc         = (const float*)d_in[6];
    const float* Wd         = (const float*)d_in[7];
    const float* fuse_w     = (const float*)d_in[8];
    const float* fuse_b     = (const float*)d_in[9];
    const float* fuse_gamma = (const float*)d_in[10];
    const float* fuse_beta  = (const float*)d_in[11];
    const float* gamma_cam  = (const float*)d_in[12];
    const float* out_w      = (const float*)d_in[13];
    const float* out_b      = (const float*)d_in[14];
    const float* out_gamma  = (const float*)d_in[15];
    const float* out_beta   = (const float*)d_in[16];
    float* out = (float*)d_out;

    k_zero<<<288, 256>>>();
    k_gram<<<dim3(72, B), 256>>>(xa, fb, fc, fd);
    k_attn<<<dim3(4, B), 256>>>(Wa, Wb, Wc, Wd, fuse_w);
    k_fuse<<<dim3(NN/64, B), 256>>>(xa, fb, fc, fd, fuse_b);
    k_bnfin<<<1, 48>>>(fuse_gamma, fuse_beta, 0);
    k_conv<<<dim3(WW/32, HH/8, B), 256>>>(xa, out_w, out_b, gamma_cam, out);
    k_bnfin<<<1, 48>>>(out_gamma, out_beta, 1);
    k_final<<<(B*C*NN)/1024, 256>>>(out);
}